// round 8
// baseline (speedup 1.0000x reference)
#include <cuda_runtime.h>
#include <cstdint>

#define N_NODES 100000
#define N_EDGES 1600000
#define HID 128

// ---------------- device scratch ----------------
__device__ int g_deg[N_NODES];
__device__ int g_off[N_NODES];
__device__ int g_cur[N_NODES];
__device__ int g_bsum[128];
__device__ int g_csr[N_EDGES];
__device__ int g_e32;
__device__ float g_x[(size_t)N_NODES * HID];   // ping-pong buffer

__device__ __forceinline__ float tf32r(float x) {
    float y;
    asm("cvt.rna.tf32.f32 %0, %1;" : "=f"(y) : "f"(x));
    return y;
}

// ---------------- edge dtype detection ----------------
__global__ void detect_k(const void* __restrict__ ei) {
    if (threadIdx.x == 0 && blockIdx.x == 0) {
        const long long* p = (const long long*)ei;
        int e32 = 0;
        for (int i = 0; i < 16; i++) {
            long long v = p[i];
            if (v < 0 || v >= N_NODES) { e32 = 1; break; }
        }
        g_e32 = e32;
    }
}
__device__ __forceinline__ int edge_at(const void* ei, long long idx) {
    if (g_e32) return ((const int*)ei)[idx];
    return (int)((const long long*)ei)[idx];
}

// ---------------- CSR build ----------------
__global__ void zero_deg_k() {
    int i = blockIdx.x * blockDim.x + threadIdx.x;
    if (i < N_NODES) g_deg[i] = 0;
}
__global__ void count_k(const void* __restrict__ ei) {
    int e = blockIdx.x * blockDim.x + threadIdx.x;
    if (e < N_EDGES) {
        int d = edge_at(ei, (long long)N_EDGES + e);
        if (d >= 0 && d < N_NODES) atomicAdd(&g_deg[d], 1);
    }
}
__global__ void scan1_k() {
    __shared__ int s[1024];
    int t = threadIdx.x;
    int i = blockIdx.x * 1024 + t;
    int v = (i < N_NODES) ? g_deg[i] : 0;
    s[t] = v;
    __syncthreads();
    for (int o = 1; o < 1024; o <<= 1) {
        int x = (t >= o) ? s[t - o] : 0;
        __syncthreads();
        s[t] += x;
        __syncthreads();
    }
    if (i < N_NODES) g_off[i] = s[t] - v;
    if (t == 1023) g_bsum[blockIdx.x] = s[1023];
}
__global__ void scan2_k(int nb) {
    __shared__ int s[128];
    int t = threadIdx.x;
    int v = (t < nb) ? g_bsum[t] : 0;
    s[t] = v;
    __syncthreads();
    for (int o = 1; o < 128; o <<= 1) {
        int x = (t >= o) ? s[t - o] : 0;
        __syncthreads();
        s[t] += x;
        __syncthreads();
    }
    if (t < nb) g_bsum[t] = s[t] - v;
}
__global__ void scan3_k() {
    int i = blockIdx.x * blockDim.x + threadIdx.x;
    if (i < N_NODES) {
        int o = g_off[i] + g_bsum[i >> 10];
        g_off[i] = o;
        g_cur[i] = o;
    }
}
__global__ void fill_k(const void* __restrict__ ei) {
    int e = blockIdx.x * blockDim.x + threadIdx.x;
    if (e < N_EDGES) {
        int d = edge_at(ei, (long long)N_EDGES + e);
        int s = edge_at(ei, e);
        if (d < 0 || d >= N_NODES) return;
        if (s < 0) s = 0;
        if (s >= N_NODES) s = N_NODES - 1;
        int p = atomicAdd(&g_cur[d], 1);
        if (p >= 0 && p < N_EDGES) g_csr[p] = s;
    }
}

// ---------------- fused gather + MLP (mma.sync tf32) ----------------
// One CTA = 128 node rows. xin and out are DISTINCT buffers (ping-pong).
// nullptr argument selects the device-global g_x buffer (address not
// queryable on host under graph capture).
//   phase G: sA[row] = tf32( xin[row] + sum_{j in N(row)} xin[j] )
//   GEMM1:   h = relu(sA @ W1 + b1)  -> written back into sA (tf32)
//   GEMM2:   out = xin + relu(h @ W2 + b2)
// 256 threads = 8 warps as 4(m) x 2(n); each warp: 32m x 64n via m16n8k8.
#define SA_STRIDE 132   // floats; conflict-free a-frag LDS
#define SW_STRIDE 136   // floats; conflict-free b-frag LDS
#define SM_B1 0
#define SM_B2 128
#define SM_A  256
#define SM_W1 (SM_A + 128 * SA_STRIDE)
#define SM_W2 (SM_W1 + 128 * SW_STRIDE)
#define SMEM_FLOATS (SM_W2 + 128 * SW_STRIDE)   // 51968 floats = 207872 B

__device__ __forceinline__ void mma8(float* d, const uint32_t* a, const uint32_t* b) {
    asm volatile(
        "mma.sync.aligned.m16n8k8.row.col.f32.tf32.tf32.f32 "
        "{%0,%1,%2,%3}, {%4,%5,%6,%7}, {%8,%9}, {%0,%1,%2,%3};\n"
        : "+f"(d[0]), "+f"(d[1]), "+f"(d[2]), "+f"(d[3])
        : "r"(a[0]), "r"(a[1]), "r"(a[2]), "r"(a[3]), "r"(b[0]), "r"(b[1]));
}

__global__ __launch_bounds__(256, 1)
void mlp_tc_k(const float* __restrict__ xin_arg,
              const float* __restrict__ W1, const float* __restrict__ b1,
              const float* __restrict__ W2, const float* __restrict__ b2,
              float* __restrict__ out_arg)
{
    // nullptr => device-global ping-pong buffer
    const float* xin = xin_arg ? xin_arg : (const float*)g_x;
    float*       out = out_arg ? out_arg : g_x;

    extern __shared__ float sm[];
    int tid = threadIdx.x, wid = tid >> 5, lane = tid & 31;
    int bm = blockIdx.x * 128;

    if (tid < 128) {
        sm[SM_B1 + tid] = b1[tid];
        sm[SM_B2 + tid] = b2[tid];
    }

    // ---- load W1/W2 tiles (tf32-rounded) ----
#pragma unroll
    for (int it = 0; it < 16; it++) {
        int idx4 = it * 256 + tid;
        int row = idx4 >> 5;
        int c4  = (idx4 & 31) * 4;
        float4 w1 = *(const float4*)(W1 + (size_t)row * 128 + c4);
        float* q1 = &sm[SM_W1 + row * SW_STRIDE + c4];
        q1[0] = tf32r(w1.x); q1[1] = tf32r(w1.y); q1[2] = tf32r(w1.z); q1[3] = tf32r(w1.w);
        float4 w2 = *(const float4*)(W2 + (size_t)row * 128 + c4);
        float* q2 = &sm[SM_W2 + row * SW_STRIDE + c4];
        q2[0] = tf32r(w2.x); q2[1] = tf32r(w2.y); q2[2] = tf32r(w2.z); q2[3] = tf32r(w2.w);
    }

    // ---- phase G: gather directly into sA (one warp per row, 16 rows/warp) ----
    {
        const float4* __restrict__ X = (const float4*)xin;
#pragma unroll 1
        for (int i = 0; i < 16; i++) {
            int row = wid * 16 + i;
            int gr = bm + row;
            float4 a = make_float4(0.f, 0.f, 0.f, 0.f);
            if (gr < N_NODES) {
                a = __ldg(&X[(size_t)gr * 32 + lane]);
                int s = g_off[gr];
                int e = s + g_deg[gr];
                int k = s;
                for (; k + 4 <= e; k += 4) {
                    int j0 = __ldg(&g_csr[k + 0]);
                    int j1 = __ldg(&g_csr[k + 1]);
                    int j2 = __ldg(&g_csr[k + 2]);
                    int j3 = __ldg(&g_csr[k + 3]);
                    float4 v0 = __ldg(&X[(size_t)j0 * 32 + lane]);
                    float4 v1 = __ldg(&X[(size_t)j1 * 32 + lane]);
                    float4 v2 = __ldg(&X[(size_t)j2 * 32 + lane]);
                    float4 v3 = __ldg(&X[(size_t)j3 * 32 + lane]);
                    a.x += (v0.x + v1.x) + (v2.x + v3.x);
                    a.y += (v0.y + v1.y) + (v2.y + v3.y);
                    a.z += (v0.z + v1.z) + (v2.z + v3.z);
                    a.w += (v0.w + v1.w) + (v2.w + v3.w);
                }
                for (; k < e; k++) {
                    int j = __ldg(&g_csr[k]);
                    float4 v = __ldg(&X[(size_t)j * 32 + lane]);
                    a.x += v.x; a.y += v.y; a.z += v.z; a.w += v.w;
                }
            }
            a.x = tf32r(a.x); a.y = tf32r(a.y); a.z = tf32r(a.z); a.w = tf32r(a.w);
            *(float4*)&sm[SM_A + row * SA_STRIDE + lane * 4] = a;
        }
    }
    __syncthreads();

    int m_base = (wid & 3) * 32;
    int n_base = (wid >> 2) * 64;
    int qr = lane >> 2;
    int qc = lane & 3;

    float acc[2][8][4];

#pragma unroll 1
    for (int pass = 0; pass < 2; pass++) {
        const int wbase = (pass == 0) ? SM_W1 : SM_W2;
#pragma unroll
        for (int mt = 0; mt < 2; mt++)
#pragma unroll
            for (int nt = 0; nt < 8; nt++)
#pragma unroll
                for (int j = 0; j < 4; j++) acc[mt][nt][j] = 0.f;

#pragma unroll
        for (int ks = 0; ks < 16; ks++) {
            int k = ks * 8;
            uint32_t afr[2][4];
#pragma unroll
            for (int mt = 0; mt < 2; mt++) {
                const float* ar = &sm[SM_A + (m_base + mt * 16 + qr) * SA_STRIDE + k + qc];
                afr[mt][0] = __float_as_uint(ar[0]);
                afr[mt][1] = __float_as_uint(ar[8 * SA_STRIDE]);
                afr[mt][2] = __float_as_uint(ar[4]);
                afr[mt][3] = __float_as_uint(ar[8 * SA_STRIDE + 4]);
            }
            uint32_t bfr[8][2];
#pragma unroll
            for (int nt = 0; nt < 8; nt++) {
                const float* br = &sm[wbase + (k + qc) * SW_STRIDE + n_base + nt * 8 + qr];
                bfr[nt][0] = __float_as_uint(br[0]);
                bfr[nt][1] = __float_as_uint(br[4 * SW_STRIDE]);
            }
#pragma unroll
            for (int mt = 0; mt < 2; mt++)
#pragma unroll
                for (int nt = 0; nt < 8; nt++)
                    mma8(acc[mt][nt], afr[mt], bfr[nt]);
        }

        if (pass == 0) {
            // ---- epilogue 1: h = tf32(relu(acc + b1)) -> back into sA ----
            __syncthreads();
#pragma unroll
            for (int mt = 0; mt < 2; mt++) {
                int r0 = m_base + mt * 16 + qr;
#pragma unroll
                for (int nt = 0; nt < 8; nt++) {
                    int c = n_base + nt * 8 + qc * 2;
                    float bx = sm[SM_B1 + c], by = sm[SM_B1 + c + 1];
                    float* p0 = &sm[SM_A + r0 * SA_STRIDE + c];
                    p0[0] = tf32r(fmaxf(acc[mt][nt][0] + bx, 0.f));
                    p0[1] = tf32r(fmaxf(acc[mt][nt][1] + by, 0.f));
                    float* p1 = &sm[SM_A + (r0 + 8) * SA_STRIDE + c];
                    p1[0] = tf32r(fmaxf(acc[mt][nt][2] + bx, 0.f));
                    p1[1] = tf32r(fmaxf(acc[mt][nt][3] + by, 0.f));
                }
            }
            __syncthreads();
        }
    }

    // ---- epilogue 2: out = xin + relu(acc + b2) ----
#pragma unroll
    for (int mt = 0; mt < 2; mt++) {
#pragma unroll
        for (int half = 0; half < 2; half++) {
            int r = bm + m_base + mt * 16 + qr + half * 8;
            if (r >= N_NODES) continue;
#pragma unroll
            for (int nt = 0; nt < 8; nt++) {
                int c = n_base + nt * 8 + qc * 2;
                float2 rv = *(const float2*)(xin + (size_t)r * 128 + c);
                float vx = acc[mt][nt][half * 2 + 0] + sm[SM_B2 + c];
                float vy = acc[mt][nt][half * 2 + 1] + sm[SM_B2 + c + 1];
                float2 o;
                o.x = rv.x + fmaxf(vx, 0.f);
                o.y = rv.y + fmaxf(vy, 0.f);
                *(float2*)(out + (size_t)r * 128 + c) = o;
            }
        }
    }
}

// ---------------- launch ----------------
extern "C" void kernel_launch(void* const* d_in, const int* in_sizes, int n_in,
                              void* d_out, int out_size) {
    const float* x0  = (const float*)d_in[0];
    const void*  ei  = d_in[1];
    const float* W1  = (const float*)d_in[2];
    const float* b1  = (const float*)d_in[3];
    const float* W2  = (const float*)d_in[4];
    const float* b2  = (const float*)d_in[5];
    float*       xout = (float*)d_out;

    static int smem_set = 0;
    if (!smem_set) {
        cudaFuncSetAttribute(mlp_tc_k, cudaFuncAttributeMaxDynamicSharedMemorySize,
                             SMEM_FLOATS * 4);
        smem_set = 1;
    }

    detect_k<<<1, 32>>>(ei);
    zero_deg_k<<<(N_NODES + 255) / 256, 256>>>();
    count_k<<<(N_EDGES + 255) / 256, 256>>>(ei);
    int nb = (N_NODES + 1023) / 1024;
    scan1_k<<<nb, 1024>>>();
    scan2_k<<<1, 128>>>(nb);
    scan3_k<<<(N_NODES + 255) / 256, 256>>>();
    fill_k<<<(N_EDGES + 255) / 256, 256>>>(ei);

    int mgrid = (N_NODES + 127) / 128;   // 782
    // ping-pong (nullptr = g_x): x0 -> g_x -> xout -> g_x -> xout
    mlp_tc_k<<<mgrid, 256, SMEM_FLOATS * 4>>>(
        x0, W1 + (size_t)0 * HID * HID, b1 + (size_t)0 * HID,
        W2 + (size_t)0 * HID * HID, b2 + (size_t)0 * HID, nullptr);
    mlp_tc_k<<<mgrid, 256, SMEM_FLOATS * 4>>>(
        nullptr, W1 + (size_t)1 * HID * HID, b1 + (size_t)1 * HID,
        W2 + (size_t)1 * HID * HID, b2 + (size_t)1 * HID, xout);
    mlp_tc_k<<<mgrid, 256, SMEM_FLOATS * 4>>>(
        xout, W1 + (size_t)2 * HID * HID, b1 + (size_t)2 * HID,
        W2 + (size_t)2 * HID * HID, b2 + (size_t)2 * HID, nullptr);
    mlp_tc_k<<<mgrid, 256, SMEM_FLOATS * 4>>>(
        nullptr, W1 + (size_t)3 * HID * HID, b1 + (size_t)3 * HID,
        W2 + (size_t)3 * HID * HID, b2 + (size_t)3 * HID, xout);
}

// round 9
// speedup vs baseline: 1.7807x; 1.7807x over previous
#include <cuda_runtime.h>
#include <cstdint>

#define N_NODES 100000
#define N_EDGES 1600000
#define HID 128

// ---------------- device scratch ----------------
__device__ int g_deg[N_NODES];
__device__ int g_off[N_NODES];
__device__ int g_cur[N_NODES];
__device__ int g_bsum[128];
__device__ int g_csr[N_EDGES];
__device__ int g_e32;
__device__ float g_agg[(size_t)N_NODES * HID];   // gather output (tf32-rounded)
__device__ float g_h[(size_t)N_NODES * HID];     // hidden (tf32-rounded)

__device__ __forceinline__ float tf32r(float x) {
    float y;
    asm("cvt.rna.tf32.f32 %0, %1;" : "=f"(y) : "f"(x));
    return y;
}

// ---------------- edge dtype detection ----------------
__global__ void detect_k(const void* __restrict__ ei) {
    if (threadIdx.x == 0 && blockIdx.x == 0) {
        const long long* p = (const long long*)ei;
        int e32 = 0;
        for (int i = 0; i < 16; i++) {
            long long v = p[i];
            if (v < 0 || v >= N_NODES) { e32 = 1; break; }
        }
        g_e32 = e32;
    }
}
__device__ __forceinline__ int edge_at(const void* ei, long long idx) {
    if (g_e32) return ((const int*)ei)[idx];
    return (int)((const long long*)ei)[idx];
}

// ---------------- CSR build ----------------
__global__ void zero_deg_k() {
    int i = blockIdx.x * blockDim.x + threadIdx.x;
    if (i < N_NODES) g_deg[i] = 0;
}
__global__ void count_k(const void* __restrict__ ei) {
    int e = blockIdx.x * blockDim.x + threadIdx.x;
    if (e < N_EDGES) {
        int d = edge_at(ei, (long long)N_EDGES + e);
        if (d >= 0 && d < N_NODES) atomicAdd(&g_deg[d], 1);
    }
}
__global__ void scan1_k() {
    __shared__ int s[1024];
    int t = threadIdx.x;
    int i = blockIdx.x * 1024 + t;
    int v = (i < N_NODES) ? g_deg[i] : 0;
    s[t] = v;
    __syncthreads();
    for (int o = 1; o < 1024; o <<= 1) {
        int x = (t >= o) ? s[t - o] : 0;
        __syncthreads();
        s[t] += x;
        __syncthreads();
    }
    if (i < N_NODES) g_off[i] = s[t] - v;
    if (t == 1023) g_bsum[blockIdx.x] = s[1023];
}
__global__ void scan2_k(int nb) {
    __shared__ int s[128];
    int t = threadIdx.x;
    int v = (t < nb) ? g_bsum[t] : 0;
    s[t] = v;
    __syncthreads();
    for (int o = 1; o < 128; o <<= 1) {
        int x = (t >= o) ? s[t - o] : 0;
        __syncthreads();
        s[t] += x;
        __syncthreads();
    }
    if (t < nb) g_bsum[t] = s[t] - v;
}
__global__ void scan3_k() {
    int i = blockIdx.x * blockDim.x + threadIdx.x;
    if (i < N_NODES) {
        int o = g_off[i] + g_bsum[i >> 10];
        g_off[i] = o;
        g_cur[i] = o;
    }
}
__global__ void fill_k(const void* __restrict__ ei) {
    int e = blockIdx.x * blockDim.x + threadIdx.x;
    if (e < N_EDGES) {
        int d = edge_at(ei, (long long)N_EDGES + e);
        int s = edge_at(ei, e);
        if (d < 0 || d >= N_NODES) return;
        if (s < 0) s = 0;
        if (s >= N_NODES) s = N_NODES - 1;
        int p = atomicAdd(&g_cur[d], 1);
        if (p >= 0 && p < N_EDGES) g_csr[p] = s;
    }
}

// ---------------- aggregation: one warp per node (high occupancy) ----------------
// g_agg[i] = tf32( x[i] + sum_{j in N(i)} x[j] )
__global__ void gather_k(const float* __restrict__ x) {
    int w = (blockIdx.x * blockDim.x + threadIdx.x) >> 5;
    int lane = threadIdx.x & 31;
    if (w >= N_NODES) return;
    const float4* __restrict__ X = (const float4*)x;
    float4 a = __ldg(&X[(size_t)w * 32 + lane]);
    int s = g_off[w];
    int e = s + g_deg[w];
    int k = s;
    // 8-edge unroll: 8 independent row loads in flight per lane
    for (; k + 8 <= e; k += 8) {
        int j0 = __ldg(&g_csr[k + 0]);
        int j1 = __ldg(&g_csr[k + 1]);
        int j2 = __ldg(&g_csr[k + 2]);
        int j3 = __ldg(&g_csr[k + 3]);
        int j4 = __ldg(&g_csr[k + 4]);
        int j5 = __ldg(&g_csr[k + 5]);
        int j6 = __ldg(&g_csr[k + 6]);
        int j7 = __ldg(&g_csr[k + 7]);
        float4 v0 = __ldg(&X[(size_t)j0 * 32 + lane]);
        float4 v1 = __ldg(&X[(size_t)j1 * 32 + lane]);
        float4 v2 = __ldg(&X[(size_t)j2 * 32 + lane]);
        float4 v3 = __ldg(&X[(size_t)j3 * 32 + lane]);
        float4 v4 = __ldg(&X[(size_t)j4 * 32 + lane]);
        float4 v5 = __ldg(&X[(size_t)j5 * 32 + lane]);
        float4 v6 = __ldg(&X[(size_t)j6 * 32 + lane]);
        float4 v7 = __ldg(&X[(size_t)j7 * 32 + lane]);
        a.x += ((v0.x + v1.x) + (v2.x + v3.x)) + ((v4.x + v5.x) + (v6.x + v7.x));
        a.y += ((v0.y + v1.y) + (v2.y + v3.y)) + ((v4.y + v5.y) + (v6.y + v7.y));
        a.z += ((v0.z + v1.z) + (v2.z + v3.z)) + ((v4.z + v5.z) + (v6.z + v7.z));
        a.w += ((v0.w + v1.w) + (v2.w + v3.w)) + ((v4.w + v5.w) + (v6.w + v7.w));
    }
    for (; k < e; k++) {
        int j = __ldg(&g_csr[k]);
        float4 v = __ldg(&X[(size_t)j * 32 + lane]);
        a.x += v.x; a.y += v.y; a.z += v.z; a.w += v.w;
    }
    a.x = tf32r(a.x); a.y = tf32r(a.y); a.z = tf32r(a.z); a.w = tf32r(a.w);
    ((float4*)g_agg)[(size_t)w * 32 + lane] = a;
}

// ---------------- GEMM kernel (mma.sync tf32), 64-row tiles, 2 CTA/SM ----------------
// mode 0: g_h = tf32(relu(g_agg @ W + bias))
// mode 1: out = resid + relu(g_h @ W + bias)
// 256 threads = 8 warps as 2(m) x 4(n); each warp 32m x 32n via m16n8k8.
// smem: bias(128) + sA(64 x 132) + sW(128 x 136) = 25984 floats = 103936 B.
#define SA_STRIDE 132
#define SW_STRIDE 136
#define SM_B 0
#define SM_A 128
#define SM_W (SM_A + 64 * SA_STRIDE)          // 8576
#define SMEM_FLOATS (SM_W + 128 * SW_STRIDE)  // 25984

__device__ __forceinline__ void mma8(float* d, const uint32_t* a, const uint32_t* b) {
    asm volatile(
        "mma.sync.aligned.m16n8k8.row.col.f32.tf32.tf32.f32 "
        "{%0,%1,%2,%3}, {%4,%5,%6,%7}, {%8,%9}, {%0,%1,%2,%3};\n"
        : "+f"(d[0]), "+f"(d[1]), "+f"(d[2]), "+f"(d[3])
        : "r"(a[0]), "r"(a[1]), "r"(a[2]), "r"(a[3]), "r"(b[0]), "r"(b[1]));
}

__global__ __launch_bounds__(256, 2)
void gemm_k(const float* __restrict__ W, const float* __restrict__ bias,
            const float* __restrict__ resid, float* __restrict__ out_arg,
            int mode)
{
    const float* __restrict__ A = (mode == 0) ? g_agg : g_h;
    float* __restrict__ out     = (mode == 0) ? g_h   : out_arg;

    extern __shared__ float sm[];
    int tid = threadIdx.x, wid = tid >> 5, lane = tid & 31;
    int bm = blockIdx.x * 64;

    if (tid < 128) sm[SM_B + tid] = bias[tid];

    // ---- load W tile (128 x 128, tf32-rounded) ----
#pragma unroll
    for (int it = 0; it < 16; it++) {
        int idx4 = it * 256 + tid;
        int row = idx4 >> 5;               // k index 0..127
        int c4  = (idx4 & 31) * 4;         // n index
        float4 w = *(const float4*)(W + (size_t)row * 128 + c4);
        float* q = &sm[SM_W + row * SW_STRIDE + c4];
        q[0] = tf32r(w.x); q[1] = tf32r(w.y); q[2] = tf32r(w.z); q[3] = tf32r(w.w);
    }
    // ---- load A tile (64 x 128, already tf32-rounded in gmem) ----
#pragma unroll
    for (int it = 0; it < 8; it++) {
        int idx4 = it * 256 + tid;         // 0..2047
        int row = idx4 >> 5;               // 0..63
        int c4  = (idx4 & 31) * 4;
        float4 v = make_float4(0.f, 0.f, 0.f, 0.f);
        if (bm + row < N_NODES)
            v = *(const float4*)(A + (size_t)(bm + row) * 128 + c4);
        float* p = &sm[SM_A + row * SA_STRIDE + c4];
        p[0] = v.x; p[1] = v.y; p[2] = v.z; p[3] = v.w;
    }
    __syncthreads();

    int m_base = (wid & 1) * 32;          // 2 m-groups
    int n_base = (wid >> 1) * 32;         // 4 n-groups
    int qr = lane >> 2;
    int qc = lane & 3;

    float acc[2][4][4];
#pragma unroll
    for (int mt = 0; mt < 2; mt++)
#pragma unroll
        for (int nt = 0; nt < 4; nt++)
#pragma unroll
            for (int j = 0; j < 4; j++) acc[mt][nt][j] = 0.f;

#pragma unroll
    for (int ks = 0; ks < 16; ks++) {
        int k = ks * 8;
        uint32_t afr[2][4];
#pragma unroll
        for (int mt = 0; mt < 2; mt++) {
            const float* ar = &sm[SM_A + (m_base + mt * 16 + qr) * SA_STRIDE + k + qc];
            afr[mt][0] = __float_as_uint(ar[0]);
            afr[mt][1] = __float_as_uint(ar[8 * SA_STRIDE]);
            afr[mt][2] = __float_as_uint(ar[4]);
            afr[mt][3] = __float_as_uint(ar[8 * SA_STRIDE + 4]);
        }
        uint32_t bfr[4][2];
#pragma unroll
        for (int nt = 0; nt < 4; nt++) {
            const float* br = &sm[SM_W + (k + qc) * SW_STRIDE + n_base + nt * 8 + qr];
            bfr[nt][0] = __float_as_uint(br[0]);
            bfr[nt][1] = __float_as_uint(br[4 * SW_STRIDE]);
        }
#pragma unroll
        for (int mt = 0; mt < 2; mt++)
#pragma unroll
            for (int nt = 0; nt < 4; nt++)
                mma8(acc[mt][nt], afr[mt], bfr[nt]);
    }

    // ---- epilogue ----
    if (mode == 0) {
        // g_h = tf32(relu(acc + bias))
#pragma unroll
        for (int mt = 0; mt < 2; mt++) {
#pragma unroll
            for (int half = 0; half < 2; half++) {
                int r = bm + m_base + mt * 16 + qr + half * 8;
                if (r >= N_NODES) continue;
#pragma unroll
                for (int nt = 0; nt < 4; nt++) {
                    int c = n_base + nt * 8 + qc * 2;
                    float2 o;
                    o.x = tf32r(fmaxf(acc[mt][nt][half * 2 + 0] + sm[SM_B + c], 0.f));
                    o.y = tf32r(fmaxf(acc[mt][nt][half * 2 + 1] + sm[SM_B + c + 1], 0.f));
                    *(float2*)(out + (size_t)r * 128 + c) = o;
                }
            }
        }
    } else {
        // out = resid + relu(acc + bias)   (elementwise in-place safe)
#pragma unroll
        for (int mt = 0; mt < 2; mt++) {
#pragma unroll
            for (int half = 0; half < 2; half++) {
                int r = bm + m_base + mt * 16 + qr + half * 8;
                if (r >= N_NODES) continue;
#pragma unroll
                for (int nt = 0; nt < 4; nt++) {
                    int c = n_base + nt * 8 + qc * 2;
                    float2 rv = *(const float2*)(resid + (size_t)r * 128 + c);
                    float2 o;
                    o.x = rv.x + fmaxf(acc[mt][nt][half * 2 + 0] + sm[SM_B + c], 0.f);
                    o.y = rv.y + fmaxf(acc[mt][nt][half * 2 + 1] + sm[SM_B + c + 1], 0.f);
                    *(float2*)(out + (size_t)r * 128 + c) = o;
                }
            }
        }
    }
}

// ---------------- launch ----------------
extern "C" void kernel_launch(void* const* d_in, const int* in_sizes, int n_in,
                              void* d_out, int out_size) {
    const float* x0  = (const float*)d_in[0];
    const void*  ei  = d_in[1];
    const float* W1  = (const float*)d_in[2];
    const float* b1  = (const float*)d_in[3];
    const float* W2  = (const float*)d_in[4];
    const float* b2  = (const float*)d_in[5];
    float*       xout = (float*)d_out;

    static int smem_set = 0;
    if (!smem_set) {
        cudaFuncSetAttribute(gemm_k, cudaFuncAttributeMaxDynamicSharedMemorySize,
                             SMEM_FLOATS * 4);
        smem_set = 1;
    }

    detect_k<<<1, 32>>>(ei);
    zero_deg_k<<<(N_NODES + 255) / 256, 256>>>();
    count_k<<<(N_EDGES + 255) / 256, 256>>>(ei);
    int nb = (N_NODES + 1023) / 1024;
    scan1_k<<<nb, 1024>>>();
    scan2_k<<<1, 128>>>(nb);
    scan3_k<<<(N_NODES + 255) / 256, 256>>>();
    fill_k<<<(N_EDGES + 255) / 256, 256>>>(ei);

    int ggrid = (N_NODES + 63) / 64;     // 1563
    for (int l = 0; l < 4; l++) {
        const float* xin = (l == 0) ? x0 : xout;
        gather_k<<<(N_NODES + 7) / 8, 256>>>(xin);
        gemm_k<<<ggrid, 256, SMEM_FLOATS * 4>>>(
            W1 + (size_t)l * HID * HID, b1 + (size_t)l * HID,
            nullptr, nullptr, 0);
        gemm_k<<<ggrid, 256, SMEM_FLOATS * 4>>>(
            W2 + (size_t)l * HID * HID, b2 + (size_t)l * HID,
            xin, xout, 1);
    }
}